// round 12
// baseline (speedup 1.0000x reference)
#include <cuda_runtime.h>
#include <cuda_fp16.h>
#include <cstdint>

// GAE reverse scan, 3-pass chunked linear recurrence with compressed
// intermediate. All scratch passed as __restrict__ params (R11 win: lets
// ptxas batch loads across stores). R12: pass2 reshaped to pass1's proven
// high-occupancy scalar shape (32 regs, 8 blocks/SM, CT=128, 2048 blocks).
//
//   adv_t = delta_t + c_t * adv_{t+1},  c_t = GL*(1-done_{t+1})
//   delta_t = r_t + GAMMA*v_{t+1}*(1-done_{t+1}) - v_t   (v_T=0, done_T=1)
// Output: d_out[0:T*N] = advantages, d_out[T*N:2*T*N] = advantages + values.

#define T_DIM   2048
#define N_DIM   4096

#define CT      128
#define LCH     (T_DIM / CT)        // 16 rows per chunk
#define BLOCK   256
#define MW      (N_DIM / 32)        // mask words per row

#define GAMMA_F 0.99f
#define GL_F    (0.99f * 0.95f)

// Scratch storage (no allocation allowed); accessed only via parameters.
__device__ uint32_t g_pack [T_DIM * N_DIM];   // (fp16(v)<<16) | fp16(delta)
__device__ uint32_t g_mask [T_DIM * MW];      // nonterminal bits
__device__ float2   g_AB   [CT * N_DIM];
__device__ float    g_carry[CT * N_DIM];

// ---------------------------------------------------------------------------
// Pass 1: read inputs once; emit compressed stream + per-chunk aggregates.
// ---------------------------------------------------------------------------
__global__ __launch_bounds__(BLOCK, 8)
void gae_pass1(const float* __restrict__ rew,
               const float* __restrict__ val,
               const float* __restrict__ don,
               uint32_t* __restrict__ pack,
               uint32_t* __restrict__ mask,
               float2*   __restrict__ AB)
{
    const int n  = blockIdx.x * BLOCK + threadIdx.x;
    const int k  = blockIdx.y;
    const int lo = k * LCH;
    const int hi = lo + LCH - 1;
    const int mw = n >> 5;
    const int lane0 = ((threadIdx.x & 31) == 0);

    float vn, dn;
    if (k == CT - 1) {
        vn = 0.0f; dn = 1.0f;
    } else {
        vn = val[(size_t)(hi + 1) * N_DIM + n];
        dn = don[(size_t)(hi + 1) * N_DIM + n];
    }

    float A = 0.0f, B = 1.0f;

    #pragma unroll
    for (int t = hi; t >= lo; --t) {
        const size_t idx = (size_t)t * N_DIM + n;
        const float rt = rew[idx];
        const float vt = val[idx];
        const float dt = don[idx];

        const float nt    = 1.0f - dn;
        const float delta = fmaf(GAMMA_F * nt, vn, rt) - vt;
        const float c     = GL_F * nt;

        const unsigned bal = __ballot_sync(0xffffffffu, dn < 0.5f);
        if (lane0) mask[(size_t)t * MW + mw] = bal;

        const uint32_t plo = (uint32_t)__half_as_ushort(__float2half_rn(delta));
        const uint32_t phi = (uint32_t)__half_as_ushort(__float2half_rn(vt));
        pack[idx] = (phi << 16) | plo;

        A = fmaf(c, A, delta);
        B = c * B;
        vn = vt;
        dn = dt;
    }

    AB[(size_t)k * N_DIM + n] = make_float2(A, B);
}

// ---------------------------------------------------------------------------
// Mid: per-column reverse fold over CT chunk aggregates -> carry per chunk.
// ---------------------------------------------------------------------------
__global__ __launch_bounds__(BLOCK)
void gae_mid(const float2* __restrict__ AB,
             float*        __restrict__ carry_out)
{
    const int n = blockIdx.x * BLOCK + threadIdx.x;

    float carry = 0.0f;
    #pragma unroll 8
    for (int k = CT - 1; k >= 0; --k) {
        const size_t idx = (size_t)k * N_DIM + n;
        carry_out[idx] = carry;
        const float2 ab = AB[idx];
        carry = fmaf(ab.y, carry, ab.x);
    }
}

// ---------------------------------------------------------------------------
// Pass 2: recurrence from compressed stream; same shape as pass1
// (scalar columns, CT=128, 8 blocks/SM, 2048 blocks).
// ---------------------------------------------------------------------------
__global__ __launch_bounds__(BLOCK, 8)
void gae_pass2(const uint32_t* __restrict__ pack,
               const uint32_t* __restrict__ mask,
               const float*    __restrict__ carry_in,
               float*          __restrict__ out)
{
    const int n   = blockIdx.x * BLOCK + threadIdx.x;
    const int k   = blockIdx.y;
    const int lo  = k * LCH;
    const int hi  = lo + LCH - 1;
    const int mw  = n >> 5;
    const int bit = n & 31;

    float adv = carry_in[(size_t)k * N_DIM + n];

    float* __restrict__ out_adv = out;
    float* __restrict__ out_ret = out + (size_t)T_DIM * N_DIM;

    #pragma unroll
    for (int t = hi; t >= lo; --t) {
        const size_t idx = (size_t)t * N_DIM + n;
        const uint32_t pk = pack[idx];
        const uint32_t m  = mask[(size_t)t * MW + mw];   // warp-broadcast load

        const float delta = __half2float(__ushort_as_half((unsigned short)(pk & 0xFFFFu)));
        const float vt    = __half2float(__ushort_as_half((unsigned short)(pk >> 16)));
        const float c     = ((m >> bit) & 1u) ? GL_F : 0.0f;

        adv = fmaf(c, adv, delta);

        out_adv[idx] = adv;
        out_ret[idx] = adv + vt;
    }
}

// ---------------------------------------------------------------------------
extern "C" void kernel_launch(void* const* d_in, const int* in_sizes, int n_in,
                              void* d_out, int out_size)
{
    const float* rew = (const float*)d_in[0];
    const float* val = (const float*)d_in[1];
    const float* don = (const float*)d_in[2];

    void *p_pack, *p_mask, *p_AB, *p_carry;
    cudaGetSymbolAddress(&p_pack,  g_pack);
    cudaGetSymbolAddress(&p_mask,  g_mask);
    cudaGetSymbolAddress(&p_AB,    g_AB);
    cudaGetSymbolAddress(&p_carry, g_carry);

    dim3 block(BLOCK);
    dim3 grid(N_DIM / BLOCK, CT);      // 16 x 128 = 2048 blocks

    gae_pass1<<<grid, block>>>(rew, val, don,
                               (uint32_t*)p_pack, (uint32_t*)p_mask,
                               (float2*)p_AB);
    gae_mid<<<N_DIM / BLOCK, block>>>((const float2*)p_AB, (float*)p_carry);
    gae_pass2<<<grid, block>>>((const uint32_t*)p_pack, (const uint32_t*)p_mask,
                               (const float*)p_carry, (float*)d_out);
}

// round 13
// speedup vs baseline: 1.0141x; 1.0141x over previous
#include <cuda_runtime.h>
#include <cuda_fp16.h>
#include <cstdint>

// GAE reverse scan, 3-pass chunked linear recurrence with compressed
// intermediate. R11 structure (scratch via __restrict__ params; pass2 uint2,
// 4 blocks/SM) + R13: evict-first (__stcs) output stores so the 67 MB of
// write-once output doesn't evict the L2-hot pack/mask intermediate.
//
//   adv_t = delta_t + c_t * adv_{t+1},  c_t = GL*(1-done_{t+1})
//   delta_t = r_t + GAMMA*v_{t+1}*(1-done_{t+1}) - v_t   (v_T=0, done_T=1)
// Output: d_out[0:T*N] = advantages, d_out[T*N:2*T*N] = advantages + values.

#define T_DIM   2048
#define N_DIM   4096
#define N2      (N_DIM / 2)

#define CT1     128
#define LCH1    (T_DIM / CT1)       // 16
#define CT2     64
#define LCH2    (T_DIM / CT2)       // 32

#define BLOCK   256
#define MW      (N_DIM / 32)        // mask words per row

#define GAMMA_F 0.99f
#define GL_F    (0.99f * 0.95f)

// Scratch storage (no allocation allowed); accessed only via parameters.
__device__ uint32_t g_pack [T_DIM * N_DIM];   // (fp16(v)<<16) | fp16(delta)
__device__ uint32_t g_mask [T_DIM * MW];      // nonterminal bits
__device__ float2   g_AB   [CT1 * N_DIM];
__device__ float    g_carry[CT1 * N_DIM];

// ---------------------------------------------------------------------------
// Pass 1: read inputs once; emit compressed stream + per-chunk aggregates.
// ---------------------------------------------------------------------------
__global__ __launch_bounds__(BLOCK, 8)
void gae_pass1(const float* __restrict__ rew,
               const float* __restrict__ val,
               const float* __restrict__ don,
               uint32_t* __restrict__ pack,
               uint32_t* __restrict__ mask,
               float2*   __restrict__ AB)
{
    const int n  = blockIdx.x * BLOCK + threadIdx.x;
    const int k  = blockIdx.y;
    const int lo = k * LCH1;
    const int hi = lo + LCH1 - 1;
    const int mw = n >> 5;
    const int lane0 = ((threadIdx.x & 31) == 0);

    float vn, dn;
    if (k == CT1 - 1) {
        vn = 0.0f; dn = 1.0f;
    } else {
        vn = val[(size_t)(hi + 1) * N_DIM + n];
        dn = don[(size_t)(hi + 1) * N_DIM + n];
    }

    float A = 0.0f, B = 1.0f;

    #pragma unroll
    for (int t = hi; t >= lo; --t) {
        const size_t idx = (size_t)t * N_DIM + n;
        const float rt = rew[idx];
        const float vt = val[idx];
        const float dt = don[idx];

        const float nt    = 1.0f - dn;
        const float delta = fmaf(GAMMA_F * nt, vn, rt) - vt;
        const float c     = GL_F * nt;

        const unsigned bal = __ballot_sync(0xffffffffu, dn < 0.5f);
        if (lane0) mask[(size_t)t * MW + mw] = bal;

        const uint32_t plo = (uint32_t)__half_as_ushort(__float2half_rn(delta));
        const uint32_t phi = (uint32_t)__half_as_ushort(__float2half_rn(vt));
        pack[idx] = (phi << 16) | plo;

        A = fmaf(c, A, delta);
        B = c * B;
        vn = vt;
        dn = dt;
    }

    AB[(size_t)k * N_DIM + n] = make_float2(A, B);
}

// ---------------------------------------------------------------------------
// Mid: per-column reverse fold over CT1 chunk aggregates -> carry per chunk.
// ---------------------------------------------------------------------------
__global__ __launch_bounds__(BLOCK)
void gae_mid(const float2* __restrict__ AB,
             float*        __restrict__ carry_out)
{
    const int n = blockIdx.x * BLOCK + threadIdx.x;

    float carry = 0.0f;
    #pragma unroll 8
    for (int k = CT1 - 1; k >= 0; --k) {
        const size_t idx = (size_t)k * N_DIM + n;
        carry_out[idx] = carry;
        const float2 ab = AB[idx];
        carry = fmaf(ab.y, carry, ab.x);
    }
}

// ---------------------------------------------------------------------------
// Pass 2: recurrence from compressed stream; 2 columns per thread (uint2),
// 4 blocks/SM. Evict-first output stores (write-once data stays out of L2).
// Carry entering pass2-chunk k2 == carry entering pass1-chunk 2*k2+1.
// ---------------------------------------------------------------------------
__global__ __launch_bounds__(BLOCK, 4)
void gae_pass2(const uint2*    __restrict__ pack2,
               const uint32_t* __restrict__ mask,
               const float*    __restrict__ carry_in,
               float2*         __restrict__ out)
{
    const int c2 = blockIdx.x * BLOCK + threadIdx.x;   // uint2 column
    const int k2 = blockIdx.y;
    const int lo = k2 * LCH2;
    const int hi = lo + LCH2 - 1;

    const int n0   = 2 * c2;
    const int mw   = n0 >> 5;
    const int bit0 = n0 & 31;

    float advx = carry_in[(size_t)(2 * k2 + 1) * N_DIM + n0];
    float advy = carry_in[(size_t)(2 * k2 + 1) * N_DIM + n0 + 1];

    float2* __restrict__ out_adv = out;
    float2* __restrict__ out_ret = out + (size_t)T_DIM * N2;

    #pragma unroll 8
    for (int t = hi; t >= lo; --t) {
        const size_t idx = (size_t)t * N2 + c2;
        const uint2    pk = pack2[idx];
        const uint32_t m  = mask[(size_t)t * MW + mw];

        const float dx = __half2float(__ushort_as_half((unsigned short)(pk.x & 0xFFFFu)));
        const float vx = __half2float(__ushort_as_half((unsigned short)(pk.x >> 16)));
        const float dy = __half2float(__ushort_as_half((unsigned short)(pk.y & 0xFFFFu)));
        const float vy = __half2float(__ushort_as_half((unsigned short)(pk.y >> 16)));

        const float cx = ((m >> bit0) & 1u) ? GL_F : 0.0f;
        const float cy = ((m >> (bit0 + 1)) & 1u) ? GL_F : 0.0f;

        advx = fmaf(cx, advx, dx);
        advy = fmaf(cy, advy, dy);

        __stcs(&out_adv[idx], make_float2(advx, advy));
        __stcs(&out_ret[idx], make_float2(advx + vx, advy + vy));
    }
}

// ---------------------------------------------------------------------------
extern "C" void kernel_launch(void* const* d_in, const int* in_sizes, int n_in,
                              void* d_out, int out_size)
{
    const float* rew = (const float*)d_in[0];
    const float* val = (const float*)d_in[1];
    const float* don = (const float*)d_in[2];

    void *p_pack, *p_mask, *p_AB, *p_carry;
    cudaGetSymbolAddress(&p_pack,  g_pack);
    cudaGetSymbolAddress(&p_mask,  g_mask);
    cudaGetSymbolAddress(&p_AB,    g_AB);
    cudaGetSymbolAddress(&p_carry, g_carry);

    dim3 block(BLOCK);
    dim3 grid1(N_DIM / BLOCK, CT1);    // 16 x 128
    dim3 grid2(N2 / BLOCK, CT2);       // 8 x 64

    gae_pass1<<<grid1, block>>>(rew, val, don,
                                (uint32_t*)p_pack, (uint32_t*)p_mask,
                                (float2*)p_AB);
    gae_mid<<<N_DIM / BLOCK, block>>>((const float2*)p_AB, (float*)p_carry);
    gae_pass2<<<grid2, block>>>((const uint2*)p_pack, (const uint32_t*)p_mask,
                                (const float*)p_carry, (float2*)d_out);
}

// round 14
// speedup vs baseline: 1.0272x; 1.0130x over previous
#include <cuda_runtime.h>
#include <cuda_fp16.h>
#include <cstdint>

// GAE reverse scan, 3-pass chunked linear recurrence with compressed
// intermediate (R11 structure) + R14: Programmatic Dependent Launch chaining
// so mid/pass2 launch-latency and prologue overlap the predecessor's tail.
//
//   adv_t = delta_t + c_t * adv_{t+1},  c_t = GL*(1-done_{t+1})
//   delta_t = r_t + GAMMA*v_{t+1}*(1-done_{t+1}) - v_t   (v_T=0, done_T=1)
// Output: d_out[0:T*N] = advantages, d_out[T*N:2*T*N] = advantages + values.

#define T_DIM   2048
#define N_DIM   4096
#define N2      (N_DIM / 2)

#define CT1     128
#define LCH1    (T_DIM / CT1)       // 16
#define CT2     64
#define LCH2    (T_DIM / CT2)       // 32

#define BLOCK   256
#define MW      (N_DIM / 32)        // mask words per row

#define GAMMA_F 0.99f
#define GL_F    (0.99f * 0.95f)

// Scratch storage (no allocation allowed); accessed only via parameters.
__device__ uint32_t g_pack [T_DIM * N_DIM];   // (fp16(v)<<16) | fp16(delta)
__device__ uint32_t g_mask [T_DIM * MW];      // nonterminal bits
__device__ float2   g_AB   [CT1 * N_DIM];
__device__ float    g_carry[CT1 * N_DIM];

// ---------------------------------------------------------------------------
// Pass 1: read inputs once; emit compressed stream + per-chunk aggregates.
// ---------------------------------------------------------------------------
__global__ __launch_bounds__(BLOCK, 8)
void gae_pass1(const float* __restrict__ rew,
               const float* __restrict__ val,
               const float* __restrict__ don,
               uint32_t* __restrict__ pack,
               uint32_t* __restrict__ mask,
               float2*   __restrict__ AB)
{
    const int n  = blockIdx.x * BLOCK + threadIdx.x;
    const int k  = blockIdx.y;
    const int lo = k * LCH1;
    const int hi = lo + LCH1 - 1;
    const int mw = n >> 5;
    const int lane0 = ((threadIdx.x & 31) == 0);

    float vn, dn;
    if (k == CT1 - 1) {
        vn = 0.0f; dn = 1.0f;
    } else {
        vn = val[(size_t)(hi + 1) * N_DIM + n];
        dn = don[(size_t)(hi + 1) * N_DIM + n];
    }

    float A = 0.0f, B = 1.0f;

    #pragma unroll
    for (int t = hi; t >= lo; --t) {
        const size_t idx = (size_t)t * N_DIM + n;
        const float rt = rew[idx];
        const float vt = val[idx];
        const float dt = don[idx];

        const float nt    = 1.0f - dn;
        const float delta = fmaf(GAMMA_F * nt, vn, rt) - vt;
        const float c     = GL_F * nt;

        const unsigned bal = __ballot_sync(0xffffffffu, dn < 0.5f);
        if (lane0) mask[(size_t)t * MW + mw] = bal;

        const uint32_t plo = (uint32_t)__half_as_ushort(__float2half_rn(delta));
        const uint32_t phi = (uint32_t)__half_as_ushort(__float2half_rn(vt));
        pack[idx] = (phi << 16) | plo;

        A = fmaf(c, A, delta);
        B = c * B;
        vn = vt;
        dn = dt;
    }

    AB[(size_t)k * N_DIM + n] = make_float2(A, B);

    // Let the dependent grid (mid) begin launching; our stores above are
    // visible to it after its cudaGridDependencySynchronize().
    cudaTriggerProgrammaticLaunchCompletion();
}

// ---------------------------------------------------------------------------
// Mid: per-column reverse fold over CT1 chunk aggregates -> carry per chunk.
// ---------------------------------------------------------------------------
__global__ __launch_bounds__(BLOCK)
void gae_mid(const float2* __restrict__ AB,
             float*        __restrict__ carry_out)
{
    cudaGridDependencySynchronize();   // wait for pass1's stores

    const int n = blockIdx.x * BLOCK + threadIdx.x;

    float carry = 0.0f;
    #pragma unroll 8
    for (int k = CT1 - 1; k >= 0; --k) {
        const size_t idx = (size_t)k * N_DIM + n;
        carry_out[idx] = carry;
        const float2 ab = AB[idx];
        carry = fmaf(ab.y, carry, ab.x);
    }

    cudaTriggerProgrammaticLaunchCompletion();
}

// ---------------------------------------------------------------------------
// Pass 2: recurrence from compressed stream; 2 columns per thread (uint2),
// 4 blocks/SM. Carry entering pass2-chunk k2 == carry of pass1-chunk 2*k2+1.
// ---------------------------------------------------------------------------
__global__ __launch_bounds__(BLOCK, 4)
void gae_pass2(const uint2*    __restrict__ pack2,
               const uint32_t* __restrict__ mask,
               const float*    __restrict__ carry_in,
               float2*         __restrict__ out)
{
    cudaGridDependencySynchronize();   // wait for mid's carries

    const int c2 = blockIdx.x * BLOCK + threadIdx.x;   // uint2 column
    const int k2 = blockIdx.y;
    const int lo = k2 * LCH2;
    const int hi = lo + LCH2 - 1;

    const int n0   = 2 * c2;
    const int mw   = n0 >> 5;
    const int bit0 = n0 & 31;

    float advx = carry_in[(size_t)(2 * k2 + 1) * N_DIM + n0];
    float advy = carry_in[(size_t)(2 * k2 + 1) * N_DIM + n0 + 1];

    float2* __restrict__ out_adv = out;
    float2* __restrict__ out_ret = out + (size_t)T_DIM * N2;

    #pragma unroll 8
    for (int t = hi; t >= lo; --t) {
        const size_t idx = (size_t)t * N2 + c2;
        const uint2    pk = pack2[idx];
        const uint32_t m  = mask[(size_t)t * MW + mw];

        const float dx = __half2float(__ushort_as_half((unsigned short)(pk.x & 0xFFFFu)));
        const float vx = __half2float(__ushort_as_half((unsigned short)(pk.x >> 16)));
        const float dy = __half2float(__ushort_as_half((unsigned short)(pk.y & 0xFFFFu)));
        const float vy = __half2float(__ushort_as_half((unsigned short)(pk.y >> 16)));

        const float cx = ((m >> bit0) & 1u) ? GL_F : 0.0f;
        const float cy = ((m >> (bit0 + 1)) & 1u) ? GL_F : 0.0f;

        advx = fmaf(cx, advx, dx);
        advy = fmaf(cy, advy, dy);

        out_adv[idx] = make_float2(advx, advy);
        out_ret[idx] = make_float2(advx + vx, advy + vy);
    }
}

// ---------------------------------------------------------------------------
extern "C" void kernel_launch(void* const* d_in, const int* in_sizes, int n_in,
                              void* d_out, int out_size)
{
    const float* rew = (const float*)d_in[0];
    const float* val = (const float*)d_in[1];
    const float* don = (const float*)d_in[2];

    void *p_pack, *p_mask, *p_AB, *p_carry;
    cudaGetSymbolAddress(&p_pack,  g_pack);
    cudaGetSymbolAddress(&p_mask,  g_mask);
    cudaGetSymbolAddress(&p_AB,    g_AB);
    cudaGetSymbolAddress(&p_carry, g_carry);

    // pass1: normal launch
    {
        dim3 grid(N_DIM / BLOCK, CT1);
        gae_pass1<<<grid, dim3(BLOCK)>>>(rew, val, don,
                                         (uint32_t*)p_pack, (uint32_t*)p_mask,
                                         (float2*)p_AB);
    }

    // mid: PDL-chained behind pass1
    {
        cudaLaunchConfig_t cfg = {};
        cfg.gridDim  = dim3(N_DIM / BLOCK);
        cfg.blockDim = dim3(BLOCK);
        cfg.stream   = 0;
        cudaLaunchAttribute attr[1];
        attr[0].id = cudaLaunchAttributeProgrammaticStreamSerialization;
        attr[0].val.programmaticStreamSerializationAllowed = 1;
        cfg.attrs = attr;
        cfg.numAttrs = 1;
        cudaLaunchKernelEx(&cfg, gae_mid,
                           (const float2*)p_AB, (float*)p_carry);
    }

    // pass2: PDL-chained behind mid
    {
        cudaLaunchConfig_t cfg = {};
        cfg.gridDim  = dim3(N2 / BLOCK, CT2);
        cfg.blockDim = dim3(BLOCK);
        cfg.stream   = 0;
        cudaLaunchAttribute attr[1];
        attr[0].id = cudaLaunchAttributeProgrammaticStreamSerialization;
        attr[0].val.programmaticStreamSerializationAllowed = 1;
        cfg.attrs = attr;
        cfg.numAttrs = 1;
        cudaLaunchKernelEx(&cfg, gae_pass2,
                           (const uint2*)p_pack, (const uint32_t*)p_mask,
                           (const float*)p_carry, (float2*)d_out);
    }
}

// round 15
// speedup vs baseline: 1.0343x; 1.0069x over previous
#include <cuda_runtime.h>
#include <cuda_fp16.h>
#include <cstdint>

// GAE reverse scan, 3-pass chunked linear recurrence with compressed
// intermediate (R11 base + PDL). R15: pass2 widened to 4 columns/thread
// (uint4 pack loads, STG.128 output stores) at CT2=128 to keep ~28 warps/SM.
//
//   adv_t = delta_t + c_t * adv_{t+1},  c_t = GL*(1-done_{t+1})
//   delta_t = r_t + GAMMA*v_{t+1}*(1-done_{t+1}) - v_t   (v_T=0, done_T=1)
// Output: d_out[0:T*N] = advantages, d_out[T*N:2*T*N] = advantages + values.

#define T_DIM   2048
#define N_DIM   4096
#define N4      (N_DIM / 4)

#define CT      128
#define LCH     (T_DIM / CT)        // 16 rows per chunk
#define BLOCK   256
#define MW      (N_DIM / 32)        // mask words per row

#define GAMMA_F 0.99f
#define GL_F    (0.99f * 0.95f)

// Scratch storage (no allocation allowed); accessed only via parameters.
__device__ uint32_t g_pack [T_DIM * N_DIM];   // (fp16(v)<<16) | fp16(delta)
__device__ uint32_t g_mask [T_DIM * MW];      // nonterminal bits
__device__ float2   g_AB   [CT * N_DIM];
__device__ float    g_carry[CT * N_DIM];

// ---------------------------------------------------------------------------
// Pass 1: read inputs once; emit compressed stream + per-chunk aggregates.
// ---------------------------------------------------------------------------
__global__ __launch_bounds__(BLOCK, 8)
void gae_pass1(const float* __restrict__ rew,
               const float* __restrict__ val,
               const float* __restrict__ don,
               uint32_t* __restrict__ pack,
               uint32_t* __restrict__ mask,
               float2*   __restrict__ AB)
{
    const int n  = blockIdx.x * BLOCK + threadIdx.x;
    const int k  = blockIdx.y;
    const int lo = k * LCH;
    const int hi = lo + LCH - 1;
    const int mw = n >> 5;
    const int lane0 = ((threadIdx.x & 31) == 0);

    float vn, dn;
    if (k == CT - 1) {
        vn = 0.0f; dn = 1.0f;
    } else {
        vn = val[(size_t)(hi + 1) * N_DIM + n];
        dn = don[(size_t)(hi + 1) * N_DIM + n];
    }

    float A = 0.0f, B = 1.0f;

    #pragma unroll
    for (int t = hi; t >= lo; --t) {
        const size_t idx = (size_t)t * N_DIM + n;
        const float rt = rew[idx];
        const float vt = val[idx];
        const float dt = don[idx];

        const float nt    = 1.0f - dn;
        const float delta = fmaf(GAMMA_F * nt, vn, rt) - vt;
        const float c     = GL_F * nt;

        const unsigned bal = __ballot_sync(0xffffffffu, dn < 0.5f);
        if (lane0) mask[(size_t)t * MW + mw] = bal;

        const uint32_t plo = (uint32_t)__half_as_ushort(__float2half_rn(delta));
        const uint32_t phi = (uint32_t)__half_as_ushort(__float2half_rn(vt));
        pack[idx] = (phi << 16) | plo;

        A = fmaf(c, A, delta);
        B = c * B;
        vn = vt;
        dn = dt;
    }

    AB[(size_t)k * N_DIM + n] = make_float2(A, B);

    cudaTriggerProgrammaticLaunchCompletion();
}

// ---------------------------------------------------------------------------
// Mid: per-column reverse fold over CT chunk aggregates -> carry per chunk.
// ---------------------------------------------------------------------------
__global__ __launch_bounds__(BLOCK)
void gae_mid(const float2* __restrict__ AB,
             float*        __restrict__ carry_out)
{
    cudaGridDependencySynchronize();

    const int n = blockIdx.x * BLOCK + threadIdx.x;

    float carry = 0.0f;
    #pragma unroll 8
    for (int k = CT - 1; k >= 0; --k) {
        const size_t idx = (size_t)k * N_DIM + n;
        carry_out[idx] = carry;
        const float2 ab = AB[idx];
        carry = fmaf(ab.y, carry, ab.x);
    }

    cudaTriggerProgrammaticLaunchCompletion();
}

// ---------------------------------------------------------------------------
// Pass 2: recurrence from compressed stream; 4 columns per thread (uint4),
// STG.128 output stores. CT2 == CT so carry_in[k] indexes directly.
// ---------------------------------------------------------------------------
__global__ __launch_bounds__(BLOCK, 4)
void gae_pass2(const uint4*    __restrict__ pack4,
               const uint32_t* __restrict__ mask,
               const float4*   __restrict__ carry_in,
               float4*         __restrict__ out)
{
    cudaGridDependencySynchronize();

    const int c4 = blockIdx.x * BLOCK + threadIdx.x;   // uint4 column
    const int k  = blockIdx.y;
    const int lo = k * LCH;
    const int hi = lo + LCH - 1;

    const int n0   = 4 * c4;
    const int mw   = n0 >> 5;
    const int bit0 = n0 & 31;                          // multiple of 4

    const float4 cr = carry_in[(size_t)k * N4 + c4];
    float a0 = cr.x, a1 = cr.y, a2 = cr.z, a3 = cr.w;

    float4* __restrict__ out_adv = out;
    float4* __restrict__ out_ret = out + (size_t)T_DIM * N4;

    #pragma unroll
    for (int t = hi; t >= lo; --t) {
        const size_t idx = (size_t)t * N4 + c4;
        const uint4    pk = pack4[idx];
        const uint32_t m  = mask[(size_t)t * MW + mw];

        const float d0 = __half2float(__ushort_as_half((unsigned short)(pk.x & 0xFFFFu)));
        const float v0 = __half2float(__ushort_as_half((unsigned short)(pk.x >> 16)));
        const float d1 = __half2float(__ushort_as_half((unsigned short)(pk.y & 0xFFFFu)));
        const float v1 = __half2float(__ushort_as_half((unsigned short)(pk.y >> 16)));
        const float d2 = __half2float(__ushort_as_half((unsigned short)(pk.z & 0xFFFFu)));
        const float v2 = __half2float(__ushort_as_half((unsigned short)(pk.z >> 16)));
        const float d3 = __half2float(__ushort_as_half((unsigned short)(pk.w & 0xFFFFu)));
        const float v3 = __half2float(__ushort_as_half((unsigned short)(pk.w >> 16)));

        const float c0 = ((m >> (bit0 + 0)) & 1u) ? GL_F : 0.0f;
        const float c1 = ((m >> (bit0 + 1)) & 1u) ? GL_F : 0.0f;
        const float c2 = ((m >> (bit0 + 2)) & 1u) ? GL_F : 0.0f;
        const float c3 = ((m >> (bit0 + 3)) & 1u) ? GL_F : 0.0f;

        a0 = fmaf(c0, a0, d0);
        a1 = fmaf(c1, a1, d1);
        a2 = fmaf(c2, a2, d2);
        a3 = fmaf(c3, a3, d3);

        out_adv[idx] = make_float4(a0, a1, a2, a3);
        out_ret[idx] = make_float4(a0 + v0, a1 + v1, a2 + v2, a3 + v3);
    }
}

// ---------------------------------------------------------------------------
extern "C" void kernel_launch(void* const* d_in, const int* in_sizes, int n_in,
                              void* d_out, int out_size)
{
    const float* rew = (const float*)d_in[0];
    const float* val = (const float*)d_in[1];
    const float* don = (const float*)d_in[2];

    void *p_pack, *p_mask, *p_AB, *p_carry;
    cudaGetSymbolAddress(&p_pack,  g_pack);
    cudaGetSymbolAddress(&p_mask,  g_mask);
    cudaGetSymbolAddress(&p_AB,    g_AB);
    cudaGetSymbolAddress(&p_carry, g_carry);

    // pass1: normal launch
    {
        dim3 grid(N_DIM / BLOCK, CT);
        gae_pass1<<<grid, dim3(BLOCK)>>>(rew, val, don,
                                         (uint32_t*)p_pack, (uint32_t*)p_mask,
                                         (float2*)p_AB);
    }

    // mid: PDL-chained behind pass1
    {
        cudaLaunchConfig_t cfg = {};
        cfg.gridDim  = dim3(N_DIM / BLOCK);
        cfg.blockDim = dim3(BLOCK);
        cfg.stream   = 0;
        cudaLaunchAttribute attr[1];
        attr[0].id = cudaLaunchAttributeProgrammaticStreamSerialization;
        attr[0].val.programmaticStreamSerializationAllowed = 1;
        cfg.attrs = attr;
        cfg.numAttrs = 1;
        cudaLaunchKernelEx(&cfg, gae_mid,
                           (const float2*)p_AB, (float*)p_carry);
    }

    // pass2: PDL-chained behind mid
    {
        cudaLaunchConfig_t cfg = {};
        cfg.gridDim  = dim3(N4 / BLOCK, CT);   // 4 x 128 = 512 blocks
        cfg.blockDim = dim3(BLOCK);
        cfg.stream   = 0;
        cudaLaunchAttribute attr[1];
        attr[0].id = cudaLaunchAttributeProgrammaticStreamSerialization;
        attr[0].val.programmaticStreamSerializationAllowed = 1;
        cfg.attrs = attr;
        cfg.numAttrs = 1;
        cudaLaunchKernelEx(&cfg, gae_pass2,
                           (const uint4*)p_pack, (const uint32_t*)p_mask,
                           (const float4*)p_carry, (float4*)d_out);
    }
}